// round 10
// baseline (speedup 1.0000x reference)
#include <cuda_runtime.h>
#include <cuda_bf16.h>
#include <cstdint>

// SPIL layer pipeline, R10:
//   k_pre : stage theta/phi/z -> bf16 hi/lo  |  s_i per point
//   aux<0>: g_feat = relu(cf @ phi_w + b)        [HMMA]
//   k1_rl : r_l per (n,k) masked+relu'd
//   main  : HMMA theta GEMM + softmax + agg -> g_agg, g_sumw
//   aux<1>: out = g_agg @ z_w + g_sumw * z_b     [HMMA]
// R10: 512-thread CTAs. Warp = (p_w, khalf, mhalf): 1 m-tile, 4 kc, acc=32 regs.
// 32 warps/SM (occ 2x), same barrier count, A-ldsm not duplicated, B-ldsm 2x.

#define BB 8
#define NN 4096
#define KK 32
#define CC 128
#define HH 64
#define PP 32
#define PTS 4
#define ROWS 128
#define D_THR 0.04f
#define NPTS (BB*NN)        // 32768
#define THREADS 512

__device__ float g_feat[NPTS * HH];
__device__ float g_si[NPTS];
__device__ float g_rl[NPTS * KK];
__device__ float g_agg[NPTS * CC];
__device__ float g_sumw[NPTS];
#define B_STR 72
__device__ __align__(16) __nv_bfloat16 g_thB[2 * CC * B_STR];
__device__ __align__(16) __nv_bfloat16 g_phB[2 * CC * B_STR];
__device__ __align__(16) __nv_bfloat16 g_zB [2 * CC * B_STR];

#define A_STR 136
#define SM_A_HI 0
#define SM_A_LO (SM_A_HI + ROWS * A_STR * 2)   // 34816
#define SM_B_HI (SM_A_LO + ROWS * A_STR * 2)   // 69632  (GEMM B; then D-staging)
#define SM_B_LO (SM_B_HI + CC * B_STR * 2)     // 88064
#define SM_FLT  (SM_B_LO + CC * B_STR * 2)     // 106496
#define F_FEAT 0      // 256 floats (main) / bias+sumw (aux)
#define F_RF   256    // 128
#define F_THB  384    // 64
#define SMEM_TOTAL (SM_FLT + 448 * 4)          // 108288 B -> 2 CTAs/SM
#define F_BIAS 0
#define F_SUMW 64

__device__ __forceinline__ uint32_t smem_to_u32(const void* p) {
    uint32_t a;
    asm("{ .reg .u64 t; cvta.to.shared.u64 t, %1; cvt.u32.u64 %0, t; }" : "=r"(a) : "l"(p));
    return a;
}
__device__ __forceinline__ void ldsm_x4(uint32_t* r, uint32_t addr) {
    asm volatile("ldmatrix.sync.aligned.m8n8.x4.shared.b16 {%0,%1,%2,%3}, [%4];"
                 : "=r"(r[0]), "=r"(r[1]), "=r"(r[2]), "=r"(r[3]) : "r"(addr));
}
__device__ __forceinline__ void ldsm_x4_t(uint32_t* r, uint32_t addr) {
    asm volatile("ldmatrix.sync.aligned.m8n8.x4.trans.shared.b16 {%0,%1,%2,%3}, [%4];"
                 : "=r"(r[0]), "=r"(r[1]), "=r"(r[2]), "=r"(r[3]) : "r"(addr));
}
__device__ __forceinline__ void mma16816(float* d, const uint32_t* a, const uint32_t* b) {
    asm volatile("mma.sync.aligned.m16n8k16.row.col.f32.bf16.bf16.f32 "
                 "{%0,%1,%2,%3}, {%4,%5,%6,%7}, {%8,%9}, {%0,%1,%2,%3};"
                 : "+f"(d[0]), "+f"(d[1]), "+f"(d[2]), "+f"(d[3])
                 : "r"(a[0]), "r"(a[1]), "r"(a[2]), "r"(a[3]), "r"(b[0]), "r"(b[1]));
}

// ---- Phase-1 A split: 128 rows x 128 fp32 -> sA_hi/sA_lo (512 threads, 8 iters) ----
__device__ __forceinline__ void split_A(const float* __restrict__ src,
                                        char* sA_hi, char* sA_lo, int tid) {
    const float4* ag = (const float4*)src;
    #pragma unroll
    for (int it = 0; it < 8; ++it) {
        int v4 = it * THREADS + tid;
        float4 v = __ldg(&ag[v4]);
        int flat = v4 * 4;
        int row = flat >> 7, c = flat & 127;
        __nv_bfloat162 h01 = __float22bfloat162_rn(make_float2(v.x, v.y));
        __nv_bfloat162 h23 = __float22bfloat162_rn(make_float2(v.z, v.w));
        float2 f01 = __bfloat1622float2(h01);
        float2 f23 = __bfloat1622float2(h23);
        __nv_bfloat162 l01 = __float22bfloat162_rn(make_float2(v.x - f01.x, v.y - f01.y));
        __nv_bfloat162 l23 = __float22bfloat162_rn(make_float2(v.z - f23.x, v.w - f23.y));
        uint32_t o = (uint32_t)(row * A_STR + c) * 2;
        *(__nv_bfloat162*)(sA_hi + o)     = h01;
        *(__nv_bfloat162*)(sA_hi + o + 4) = h23;
        *(__nv_bfloat162*)(sA_lo + o)     = l01;
        *(__nv_bfloat162*)(sA_lo + o + 4) = l23;
    }
}

// ---- GEMM core: warp (p_w, khalf, mhalf) does 4 kc x 1 mtile x 8 nt x 3 passes.
// After return, khalf==0 warps hold the full D for their 16-row tile.
__device__ __forceinline__ void gemm_core(uint32_t sbase, int p_w, int khalf, int mhalf,
                                          int lid, float acc[8][4]) {
    #pragma unroll
    for (int nt = 0; nt < 8; ++nt)
        #pragma unroll
        for (int e = 0; e < 4; ++e) acc[nt][e] = 0.f;

    const uint32_t a_row  = (uint32_t)(p_w * 32 + mhalf * 16 + (lid & 15));
    const uint32_t a_colq = (uint32_t)((lid >> 4) * 8);
    const uint32_t aoff   = (a_row * A_STR + a_colq) * 2;
    const uint32_t b_rowl = (uint32_t)(lid & 15);
    const uint32_t b_colq = (uint32_t)((lid >> 4) * 8);

    #pragma unroll
    for (int j = 0; j < 4; ++j) {
        const int kc = 4 * khalf + j;
        uint32_t ah[4], al[4];
        ldsm_x4(ah, sbase + SM_A_HI + aoff + (uint32_t)(kc * 32));
        ldsm_x4(al, sbase + SM_A_LO + aoff + (uint32_t)(kc * 32));

        uint32_t brow = (uint32_t)(kc * 16) + b_rowl;
        uint32_t bh[8][2], bl[8][2];
        #pragma unroll
        for (int p = 0; p < 4; ++p) {
            uint32_t bo = (brow * B_STR + 16 * p + b_colq) * 2;
            uint32_t r[4];
            ldsm_x4_t(r, sbase + SM_B_HI + bo);
            bh[2*p][0] = r[0]; bh[2*p][1] = r[1]; bh[2*p+1][0] = r[2]; bh[2*p+1][1] = r[3];
            ldsm_x4_t(r, sbase + SM_B_LO + bo);
            bl[2*p][0] = r[0]; bl[2*p][1] = r[1]; bl[2*p+1][0] = r[2]; bl[2*p+1][1] = r[3];
        }
        #pragma unroll
        for (int nt = 0; nt < 8; ++nt) {
            mma16816(acc[nt], ah, bh[nt]);
            mma16816(acc[nt], ah, bl[nt]);
            mma16816(acc[nt], al, bh[nt]);
        }
    }
    __syncthreads();   // B ldsm done -> B region becomes D staging

    // 2-way K reduction: slot (p_w, mhalf) = 4KB, 8 slots = 32KB in dead B region
    uint32_t stage = sbase + SM_B_HI + (uint32_t)((p_w * 2 + mhalf) * 4096) + (uint32_t)(lid * 16);
    if (khalf == 1) {
        #pragma unroll
        for (int nt = 0; nt < 8; ++nt)
            asm volatile("st.shared.v4.f32 [%0], {%1,%2,%3,%4};"
                         :: "r"(stage + nt * 512),
                            "f"(acc[nt][0]), "f"(acc[nt][1]),
                            "f"(acc[nt][2]), "f"(acc[nt][3]) : "memory");
    }
    __syncthreads();
    if (khalf == 0) {
        #pragma unroll
        for (int nt = 0; nt < 8; ++nt) {
            float p0, p1, p2, p3;
            asm volatile("ld.shared.v4.f32 {%0,%1,%2,%3}, [%4];"
                         : "=f"(p0), "=f"(p1), "=f"(p2), "=f"(p3)
                         : "r"(stage + nt * 512));
            acc[nt][0] += p0; acc[nt][1] += p1;
            acc[nt][2] += p2; acc[nt][3] += p3;
        }
    }
}

// ---------- k_pre: bf16 weight staging (theta/phi/z) + s_i ----------
#define SI_BLKS  (NPTS / 256)    // 128
__global__ void __launch_bounds__(256) k_pre(const float* __restrict__ cxyz,
                                             const float* __restrict__ m1w,
                                             const float* __restrict__ m1b,
                                             const float* __restrict__ psiw,
                                             const float* __restrict__ tw,
                                             const float* __restrict__ phiw,
                                             const float* __restrict__ zw) {
    int blk = blockIdx.x;
    int tid = threadIdx.x;
    if (blk < SI_BLKS) {
        __shared__ float sw[96], sb2[32], sp[32];
        if (tid < 96) sw[tid] = m1w[tid];
        if (tid < 32) { sb2[tid] = m1b[tid]; sp[tid] = psiw[tid]; }
        __syncthreads();
        int id = blk * 256 + tid;
        float x = cxyz[id * 3], y = cxyz[id * 3 + 1], z = cxyz[id * 3 + 2];
        float si = 0.f;
        #pragma unroll
        for (int d = 0; d < PP; ++d) {
            float pi = fmaf(x, sw[d], fmaf(y, sw[32 + d], fmaf(z, sw[64 + d], sb2[d])));
            si = fmaf(fmaxf(pi, 0.f), sp[d], si);
        }
        g_si[id] = si;
        return;
    }
    blk -= SI_BLKS;
    int m = blk >> 5;                 // 0: theta, 1: phi, 2: z
    int id = (blk & 31) * 256 + tid;
    const float* src = (m == 0) ? tw : (m == 1) ? phiw : zw;
    __nv_bfloat16* dst = (m == 0) ? g_thB : (m == 1) ? g_phB : g_zB;
    int c = id >> 6, h = id & 63;
    float v = src[id];
    __nv_bfloat16 hi = __float2bfloat16_rn(v);
    __nv_bfloat16 lo = __float2bfloat16_rn(v - __bfloat162float(hi));
    dst[c * B_STR + h] = hi;
    dst[CC * B_STR + c * B_STR + h] = lo;
}

// ---------- k1_rl ----------
__global__ void __launch_bounds__(256) k1_rl(const float* __restrict__ cxyz,
                                             const float* __restrict__ nxyz,
                                             const float* __restrict__ m2w,
                                             const float* __restrict__ m2b,
                                             const float* __restrict__ psiw,
                                             const float* __restrict__ psib) {
    __shared__ float sw[96], sb[32], sp[32], spb;
    int tid = threadIdx.x;
    if (tid < 96) sw[tid] = m2w[tid];
    if (tid < 32) { sb[tid] = m2b[tid]; sp[tid] = psiw[32 + tid]; }
    if (tid == 0) spb = psib[0];
    __syncthreads();
    int g = blockIdx.x * 256 + tid;
    int nl = g >> 5;
    float nx = nxyz[g * 3], ny = nxyz[g * 3 + 1], nz = nxyz[g * 3 + 2];
    float cx = cxyz[nl * 3], cy = cxyz[nl * 3 + 1], cz = cxyz[nl * 3 + 2];
    float sj = 0.f;
    #pragma unroll
    for (int d = 0; d < PP; ++d) {
        float pj = fmaf(nx, sw[d], fmaf(ny, sw[32 + d], fmaf(nz, sw[64 + d], sb[d])));
        sj = fmaf(fmaxf(pj, 0.f), sp[d], sj);
    }
    float dx = cx - nx, dy = cy - ny, dz = cz - nz;
    float dist = sqrtf(dx * dx + dy * dy + dz * dz);
    bool masked = (cz == nz) && (dist > D_THR);
    g_rl[g] = fmaxf(g_si[nl] + sj + spb, 0.f) * (masked ? 0.f : 1.f);
}

// ---------- aux HMMA GEMM: 128 rows/CTA ----------
// MODE 0: g_feat = relu(cf @ phi_w + bias)
// MODE 1: outp   = g_agg @ z_w + g_sumw[row] * bias
template <int MODE>
__global__ void __launch_bounds__(THREADS, 2)
aux_gemm(const float* __restrict__ Ain, const float* __restrict__ bias,
         float* __restrict__ outparam)
{
    extern __shared__ char smem[];
    const uint32_t sbase = smem_to_u32(smem);
    char* sA_hi = smem + SM_A_HI;
    char* sA_lo = smem + SM_A_LO;
    float* s_f    = (float*)(smem + SM_FLT);
    float* s_bias = s_f + F_BIAS;
    float* s_sumw = s_f + F_SUMW;

    const int tid = threadIdx.x;
    const int wid = tid >> 5;
    const int lid = tid & 31;
    const int p_w   = wid & 3;
    const int khalf = (wid >> 2) & 1;
    const int mhalf = wid >> 3;
    const int r0 = blockIdx.x * 128;

    const float* Asrc = (MODE == 0) ? Ain : g_agg;
    const __nv_bfloat16* Bsrc = (MODE == 0) ? g_phB : g_zB;
    float* outp = (MODE == 0) ? g_feat : outparam;

    split_A(Asrc + (size_t)r0 * CC, sA_hi, sA_lo, tid);
    {
        const uint4* tb = (const uint4*)Bsrc;
        uint4* bd = (uint4*)(smem + SM_B_HI);
        for (int i = tid; i < 2304; i += THREADS) bd[i] = __ldg(&tb[i]);
        if (tid < 64) s_bias[tid] = bias[tid];
        if (MODE == 1 && tid < 128) s_sumw[tid] = g_sumw[r0 + tid];
    }
    __syncthreads();

    float acc[8][4];
    gemm_core(sbase, p_w, khalf, mhalf, lid, acc);

    if (khalf == 0) {
        const int g = lid >> 2, t = lid & 3;
        #pragma unroll
        for (int nt = 0; nt < 8; ++nt) {
            int h = nt * 8 + t * 2;
            float b0 = s_bias[h], b1 = s_bias[h + 1];
            int lr0 = p_w * 32 + mhalf * 16 + g;
            int lr1 = lr0 + 8;
            float v00, v01, v10, v11;
            if (MODE == 0) {
                v00 = fmaxf(acc[nt][0] + b0, 0.f);
                v01 = fmaxf(acc[nt][1] + b1, 0.f);
                v10 = fmaxf(acc[nt][2] + b0, 0.f);
                v11 = fmaxf(acc[nt][3] + b1, 0.f);
            } else {
                float s0 = s_sumw[lr0], s1 = s_sumw[lr1];
                v00 = fmaf(s0, b0, acc[nt][0]);
                v01 = fmaf(s0, b1, acc[nt][1]);
                v10 = fmaf(s1, b0, acc[nt][2]);
                v11 = fmaf(s1, b1, acc[nt][3]);
            }
            *(float2*)&outp[(size_t)(r0 + lr0) * HH + h] = make_float2(v00, v01);
            *(float2*)&outp[(size_t)(r0 + lr1) * HH + h] = make_float2(v10, v11);
        }
    }
}

// ---------- main: HMMA theta GEMM + softmax + aggregation ----------
__global__ void __launch_bounds__(THREADS, 2)
spil_main(const float* __restrict__ neighbor_features,
          const float* __restrict__ theta_b)
{
    extern __shared__ char smem[];
    const uint32_t sbase = smem_to_u32(smem);
    char* sA_hi = smem + SM_A_HI;
    char* sA_lo = smem + SM_A_LO;
    float* s_f    = (float*)(smem + SM_FLT);
    float* s_feat = s_f + F_FEAT;
    float* s_rf   = s_f + F_RF;
    float* s_thb  = s_f + F_THB;

    const int tid = threadIdx.x;
    const int wid = tid >> 5;
    const int lid = tid & 31;
    const int p_w   = wid & 3;
    const int khalf = (wid >> 2) & 1;
    const int mhalf = wid >> 3;
    const int cq    = wid >> 2;      // 0,1: softmax+agg warps (mhalf==0)
    const int bn0 = blockIdx.x * PTS;

    const float r_l = (cq < 2) ? __ldg(&g_rl[blockIdx.x * 128 + p_w * 32 + lid]) : 0.f;

    split_A(neighbor_features + (size_t)bn0 * KK * CC, sA_hi, sA_lo, tid);
    {
        const uint4* tb = (const uint4*)g_thB;
        uint4* bd = (uint4*)(smem + SM_B_HI);
        for (int i = tid; i < 2304; i += THREADS) bd[i] = __ldg(&tb[i]);
        if (tid < 64)
            ((uint4*)s_feat)[tid] = __ldg(&((const uint4*)(g_feat + (size_t)bn0 * HH))[tid]);
        if (tid < 64) s_thb[tid] = theta_b[tid];
    }
    __syncthreads();

    float acc[8][4];
    gemm_core(sbase, p_w, khalf, mhalf, lid, acc);

    // r_f reduction: khalf==0 warps, each owns 16 rows of its point
    if (khalf == 0) {
        const int g = lid >> 2, t = lid & 3;
        const float* fp = s_feat + p_w * HH;
        float rA = 0.f, rB = 0.f;
        #pragma unroll
        for (int nt = 0; nt < 8; ++nt) {
            int h0 = nt * 8 + t * 2, h1 = h0 + 1;
            float tb0 = s_thb[h0], tb1 = s_thb[h1];
            float f0 = fp[h0], f1 = fp[h1];
            rA = fmaf(fmaxf(acc[nt][0] + tb0, 0.f), f0, rA);
            rA = fmaf(fmaxf(acc[nt][1] + tb1, 0.f), f1, rA);
            rB = fmaf(fmaxf(acc[nt][2] + tb0, 0.f), f0, rB);
            rB = fmaf(fmaxf(acc[nt][3] + tb1, 0.f), f1, rB);
        }
        rA += __shfl_xor_sync(0xffffffffu, rA, 1);
        rA += __shfl_xor_sync(0xffffffffu, rA, 2);
        rB += __shfl_xor_sync(0xffffffffu, rB, 1);
        rB += __shfl_xor_sync(0xffffffffu, rB, 2);
        if (t == 0) {
            s_rf[p_w * 32 + mhalf * 16 + g]     = rA;
            s_rf[p_w * 32 + mhalf * 16 + g + 8] = rB;
        }
    }
    __syncthreads();

    // softmax + aggregation: cq<2 warps; column half = cq
    if (cq < 2) {
        float rf = s_rf[p_w * 32 + lid] * 0.125f;
        float m = rf;
        #pragma unroll
        for (int ofs = 16; ofs > 0; ofs >>= 1) m = fmaxf(m, __shfl_xor_sync(0xffffffffu, m, ofs));
        float e = r_l * __expf(rf - m);
        float s = e;
        #pragma unroll
        for (int ofs = 16; ofs > 0; ofs >>= 1) s += __shfl_xor_sync(0xffffffffu, s, ofs);
        float denom = s + 1e-8f;
        float Wk = e / denom;
        if (cq == 0 && lid == 0) g_sumw[bn0 + p_w] = s / denom;

        float2 a01 = make_float2(0.f, 0.f);
        const uint32_t co = (uint32_t)(128 * cq + 4 * lid);
        #pragma unroll
        for (int k = 0; k < KK; ++k) {
            float wk = __shfl_sync(0xffffffffu, Wk, k);
            uint32_t o = (uint32_t)((p_w * KK + k) * A_STR) * 2 + co;
            float2 h0 = __bfloat1622float2(*(__nv_bfloat162*)(sA_hi + o));
            float2 l0 = __bfloat1622float2(*(__nv_bfloat162*)(sA_lo + o));
            a01.x = fmaf(wk, h0.x + l0.x, a01.x);
            a01.y = fmaf(wk, h0.y + l0.y, a01.y);
        }
        float* dst = g_agg + (size_t)(bn0 + p_w) * CC + 64 * cq;
        *(float2*)&dst[2 * lid] = a01;
    }
}

extern "C" void kernel_launch(void* const* d_in, const int* in_sizes, int n_in,
                              void* d_out, int out_size)
{
    (void)in_sizes; (void)n_in; (void)out_size;
    const float* center_xyz        = (const float*)d_in[0];
    const float* center_features   = (const float*)d_in[1];
    const float* neighbor_xyz      = (const float*)d_in[2];
    const float* neighbor_features = (const float*)d_in[3];
    const float* phi_w   = (const float*)d_in[4];
    const float* phi_b   = (const float*)d_in[5];
    const float* theta_w = (const float*)d_in[6];
    const float* theta_b = (const float*)d_in[7];
    const float* m1_w    = (const float*)d_in[8];
    const float* m1_b    = (const float*)d_in[9];
    const float* m2_w    = (const float*)d_in[10];
    const float* m2_b    = (const float*)d_in[11];
    const float* psi_w   = (const float*)d_in[12];
    const float* psi_b   = (const float*)d_in[13];
    const float* z_w     = (const float*)d_in[14];
    const float* z_b     = (const float*)d_in[15];
    float* out = (float*)d_out;

    cudaFuncSetAttribute(spil_main, cudaFuncAttributeMaxDynamicSharedMemorySize, SMEM_TOTAL);
    cudaFuncSetAttribute(aux_gemm<0>, cudaFuncAttributeMaxDynamicSharedMemorySize, SMEM_TOTAL);
    cudaFuncSetAttribute(aux_gemm<1>, cudaFuncAttributeMaxDynamicSharedMemorySize, SMEM_TOTAL);

    k_pre<<<SI_BLKS + 96, 256>>>(center_xyz, m1_w, m1_b, psi_w, theta_w, phi_w, z_w);
    aux_gemm<0><<<NPTS / 128, THREADS, SMEM_TOTAL>>>(center_features, phi_b, out);
    k1_rl<<<NPTS * KK / 256, 256>>>(center_xyz, neighbor_xyz, m2_w, m2_b, psi_w, psi_b);
    spil_main<<<NPTS / PTS, THREADS, SMEM_TOTAL>>>(neighbor_features, theta_b);
    aux_gemm<1><<<NPTS / 128, THREADS, SMEM_TOTAL>>>(center_features, z_b, out);
}

// round 11
// speedup vs baseline: 1.3754x; 1.3754x over previous
#include <cuda_runtime.h>
#include <cuda_fp16.h>
#include <cstdint>

// SPIL layer pipeline, R11 = R9 structure with fp16 2-pass GEMM.
//   k_pre : stage theta/phi/z -> fp16 (single, no lo)  |  s_i per point
//   aux<0>: g_feat = relu(cf @ phi_w + b)        [HMMA fp16 2-pass]
//   k1_rl : r_l per (n,k) masked+relu'd
//   main  : K-split HMMA theta GEMM + softmax + agg -> g_agg, g_sumw
//   aux<1>: out = g_agg @ z_w + g_sumw * z_b     [HMMA fp16 2-pass]
// 2-pass: D = (A_hi + A_lo) * B_fp16. B-rounding 2^-12 rms over K=128
// -> predicted rel_err ~1.5e-4 (bf16 3-pass model predicted 4e-6, measured 5.3e-6).
// Cuts 1/3 of MMAs, 1/2 of B-ldsm, 1/2 of B smem vs R9. D-reduction staged in
// the dead 18KB B region in 2 rounds. Occupancy deliberately unchanged
// (R5+R10: occupancy-for-traffic trades regress).

#define BB 8
#define NN 4096
#define KK 32
#define CC 128
#define HH 64
#define PP 32
#define PTS 4
#define ROWS 128
#define D_THR 0.04f
#define NPTS (BB*NN)        // 32768

__device__ float g_feat[NPTS * HH];
__device__ float g_si[NPTS];
__device__ float g_rl[NPTS * KK];
__device__ float g_agg[NPTS * CC];
__device__ float g_sumw[NPTS];
#define B_STR 72
__device__ __align__(16) __half g_thB[CC * B_STR];
__device__ __align__(16) __half g_phB[CC * B_STR];
__device__ __align__(16) __half g_zB [CC * B_STR];

#define A_STR 136
#define SM_A_HI 0
#define SM_A_LO (SM_A_HI + ROWS * A_STR * 2)   // 34816
#define SM_B_HI (SM_A_LO + ROWS * A_STR * 2)   // 69632 (B fp16; then D staging x2 rounds)
#define SM_FLT  (SM_B_HI + CC * B_STR * 2)     // 88064
#define F_FEAT 0      // 256 floats (main) / bias+sumw (aux)
#define F_RF   256    // 128
#define F_THB  384    // 64
#define SMEM_TOTAL (SM_FLT + 448 * 4)          // 89856 B -> 2 CTAs/SM
#define F_BIAS 0
#define F_SUMW 64

__device__ __forceinline__ uint32_t smem_to_u32(const void* p) {
    uint32_t a;
    asm("{ .reg .u64 t; cvta.to.shared.u64 t, %1; cvt.u32.u64 %0, t; }" : "=r"(a) : "l"(p));
    return a;
}
__device__ __forceinline__ void ldsm_x4(uint32_t* r, uint32_t addr) {
    asm volatile("ldmatrix.sync.aligned.m8n8.x4.shared.b16 {%0,%1,%2,%3}, [%4];"
                 : "=r"(r[0]), "=r"(r[1]), "=r"(r[2]), "=r"(r[3]) : "r"(addr));
}
__device__ __forceinline__ void ldsm_x4_t(uint32_t* r, uint32_t addr) {
    asm volatile("ldmatrix.sync.aligned.m8n8.x4.trans.shared.b16 {%0,%1,%2,%3}, [%4];"
                 : "=r"(r[0]), "=r"(r[1]), "=r"(r[2]), "=r"(r[3]) : "r"(addr));
}
__device__ __forceinline__ void mma16816(float* d, const uint32_t* a, const uint32_t* b) {
    asm volatile("mma.sync.aligned.m16n8k16.row.col.f32.f16.f16.f32 "
                 "{%0,%1,%2,%3}, {%4,%5,%6,%7}, {%8,%9}, {%0,%1,%2,%3};"
                 : "+f"(d[0]), "+f"(d[1]), "+f"(d[2]), "+f"(d[3])
                 : "r"(a[0]), "r"(a[1]), "r"(a[2]), "r"(a[3]), "r"(b[0]), "r"(b[1]));
}

// ---- Phase-1 A split: 128 rows x 128 fp32 -> fp16 hi/lo (256 threads, 16 iters) ----
__device__ __forceinline__ void split_A(const float* __restrict__ src,
                                        char* sA_hi, char* sA_lo, int tid) {
    const float4* ag = (const float4*)src;
    #pragma unroll
    for (int it = 0; it < 16; ++it) {
        int v4 = it * 256 + tid;
        float4 v = __ldg(&ag[v4]);
        int flat = v4 * 4;
        int row = flat >> 7, c = flat & 127;
        __half2 h01 = __float22half2_rn(make_float2(v.x, v.y));
        __half2 h23 = __float22half2_rn(make_float2(v.z, v.w));
        float2 f01 = __half22float2(h01);
        float2 f23 = __half22float2(h23);
        __half2 l01 = __float22half2_rn(make_float2(v.x - f01.x, v.y - f01.y));
        __half2 l23 = __float22half2_rn(make_float2(v.z - f23.x, v.w - f23.y));
        uint32_t o = (uint32_t)(row * A_STR + c) * 2;
        *(__half2*)(sA_hi + o)     = h01;
        *(__half2*)(sA_hi + o + 4) = h23;
        *(__half2*)(sA_lo + o)     = l01;
        *(__half2*)(sA_lo + o + 4) = l23;
    }
}

// K-split 2-pass GEMM core + 2-round smem D-reduction (staged in B region).
// After return, khalf=0 warps hold full D.
__device__ __forceinline__ void gemm_ksplit(uint32_t sbase, int p_w, int khalf,
                                            int lid, float acc[2][8][4]) {
    #pragma unroll
    for (int mt = 0; mt < 2; ++mt)
        #pragma unroll
        for (int nt = 0; nt < 8; ++nt)
            #pragma unroll
            for (int e = 0; e < 4; ++e) acc[mt][nt][e] = 0.f;

    const uint32_t a_row  = (uint32_t)(p_w * 32 + (lid & 15));
    const uint32_t a_colq = (uint32_t)((lid >> 4) * 8);
    const uint32_t aoff   = (a_row * A_STR + a_colq) * 2;
    const uint32_t b_rowl = (uint32_t)(lid & 15);
    const uint32_t b_colq = (uint32_t)((lid >> 4) * 8);

    #pragma unroll
    for (int j = 0; j < 4; ++j) {
        const int kc = 4 * khalf + j;
        uint32_t aA = sbase + SM_A_HI + aoff + (uint32_t)(kc * 32);
        uint32_t aL = sbase + SM_A_LO + aoff + (uint32_t)(kc * 32);
        uint32_t ah[2][4], al[2][4];
        ldsm_x4(ah[0], aA);
        ldsm_x4(ah[1], aA + 16 * A_STR * 2);
        ldsm_x4(al[0], aL);
        ldsm_x4(al[1], aL + 16 * A_STR * 2);

        uint32_t brow = (uint32_t)(kc * 16) + b_rowl;
        uint32_t bh[8][2];
        #pragma unroll
        for (int p = 0; p < 4; ++p) {
            uint32_t bo = (brow * B_STR + 16 * p + b_colq) * 2;
            uint32_t r[4];
            ldsm_x4_t(r, sbase + SM_B_HI + bo);
            bh[2*p][0] = r[0]; bh[2*p][1] = r[1]; bh[2*p+1][0] = r[2]; bh[2*p+1][1] = r[3];
        }
        #pragma unroll
        for (int mt = 0; mt < 2; ++mt)
            #pragma unroll
            for (int nt = 0; nt < 8; ++nt) {
                mma16816(acc[mt][nt], ah[mt], bh[nt]);
                mma16816(acc[mt][nt], al[mt], bh[nt]);
            }
    }
    __syncthreads();   // all B ldsm done -> B region (18KB) becomes D staging

    // 2-round reduction: per round 4 slots x 4KB = 16KB <= 18KB
    uint32_t stage = sbase + SM_B_HI + (uint32_t)(p_w * 4096) + (uint32_t)(lid * 16);
    #pragma unroll
    for (int mt = 0; mt < 2; ++mt) {
        if (khalf == 1) {
            #pragma unroll
            for (int nt = 0; nt < 8; ++nt)
                asm volatile("st.shared.v4.f32 [%0], {%1,%2,%3,%4};"
                             :: "r"(stage + nt * 512),
                                "f"(acc[mt][nt][0]), "f"(acc[mt][nt][1]),
                                "f"(acc[mt][nt][2]), "f"(acc[mt][nt][3]) : "memory");
        }
        __syncthreads();
        if (khalf == 0) {
            #pragma unroll
            for (int nt = 0; nt < 8; ++nt) {
                float p0, p1, p2, p3;
                asm volatile("ld.shared.v4.f32 {%0,%1,%2,%3}, [%4];"
                             : "=f"(p0), "=f"(p1), "=f"(p2), "=f"(p3)
                             : "r"(stage + nt * 512));
                acc[mt][nt][0] += p0; acc[mt][nt][1] += p1;
                acc[mt][nt][2] += p2; acc[mt][nt][3] += p3;
            }
        }
        __syncthreads();
    }
}

// ---------- k_pre: fp16 weight staging (theta/phi/z) + s_i ----------
#define SI_BLKS  (NPTS / 256)    // 128
__global__ void __launch_bounds__(256) k_pre(const float* __restrict__ cxyz,
                                             const float* __restrict__ m1w,
                                             const float* __restrict__ m1b,
                                             const float* __restrict__ psiw,
                                             const float* __restrict__ tw,
                                             const float* __restrict__ phiw,
                                             const float* __restrict__ zw) {
    int blk = blockIdx.x;
    int tid = threadIdx.x;
    if (blk < SI_BLKS) {
        __shared__ float sw[96], sb2[32], sp[32];
        if (tid < 96) sw[tid] = m1w[tid];
        if (tid < 32) { sb2[tid] = m1b[tid]; sp[tid] = psiw[tid]; }
        __syncthreads();
        int id = blk * 256 + tid;
        float x = cxyz[id * 3], y = cxyz[id * 3 + 1], z = cxyz[id * 3 + 2];
        float si = 0.f;
        #pragma unroll
        for (int d = 0; d < PP; ++d) {
            float pi = fmaf(x, sw[d], fmaf(y, sw[32 + d], fmaf(z, sw[64 + d], sb2[d])));
            si = fmaf(fmaxf(pi, 0.f), sp[d], si);
        }
        g_si[id] = si;
        return;
    }
    blk -= SI_BLKS;
    int m = blk >> 5;                 // 0: theta, 1: phi, 2: z
    int id = (blk & 31) * 256 + tid;
    const float* src = (m == 0) ? tw : (m == 1) ? phiw : zw;
    __half* dst = (m == 0) ? g_thB : (m == 1) ? g_phB : g_zB;
    int c = id >> 6, h = id & 63;
    dst[c * B_STR + h] = __float2half_rn(src[id]);
}

// ---------- k1_rl ----------
__global__ void __launch_bounds__(256) k1_rl(const float* __restrict__ cxyz,
                                             const float* __restrict__ nxyz,
                                             const float* __restrict__ m2w,
                                             const float* __restrict__ m2b,
                                             const float* __restrict__ psiw,
                                             const float* __restrict__ psib) {
    __shared__ float sw[96], sb[32], sp[32], spb;
    int tid = threadIdx.x;
    if (tid < 96) sw[tid] = m2w[tid];
    if (tid < 32) { sb[tid] = m2b[tid]; sp[tid] = psiw[32 + tid]; }
    if (tid == 0) spb = psib[0];
    __syncthreads();
    int g = blockIdx.x * 256 + tid;
    int nl = g >> 5;
    float nx = nxyz[g * 3], ny = nxyz[g * 3 + 1], nz = nxyz[g * 3 + 2];
    float cx = cxyz[nl * 3], cy = cxyz[nl * 3 + 1], cz = cxyz[nl * 3 + 2];
    float sj = 0.f;
    #pragma unroll
    for (int d = 0; d < PP; ++d) {
        float pj = fmaf(nx, sw[d], fmaf(ny, sw[32 + d], fmaf(nz, sw[64 + d], sb[d])));
        sj = fmaf(fmaxf(pj, 0.f), sp[d], sj);
    }
    float dx = cx - nx, dy = cy - ny, dz = cz - nz;
    float dist = sqrtf(dx * dx + dy * dy + dz * dz);
    bool masked = (cz == nz) && (dist > D_THR);
    g_rl[g] = fmaxf(g_si[nl] + sj + spb, 0.f) * (masked ? 0.f : 1.f);
}

// ---------- aux HMMA GEMM: 128 rows/CTA, [128x128]@[128x64] ----------
// MODE 0: g_feat = relu(cf @ phi_w + bias)
// MODE 1: outp   = g_agg @ z_w + g_sumw[row] * bias
template <int MODE>
__global__ void __launch_bounds__(256, 2)
aux_gemm(const float* __restrict__ Ain, const float* __restrict__ bias,
         float* __restrict__ outparam)
{
    extern __shared__ char smem[];
    const uint32_t sbase = smem_to_u32(smem);
    char* sA_hi = smem + SM_A_HI;
    char* sA_lo = smem + SM_A_LO;
    float* s_f    = (float*)(smem + SM_FLT);
    float* s_bias = s_f + F_BIAS;
    float* s_sumw = s_f + F_SUMW;

    const int tid = threadIdx.x;
    const int wid = tid >> 5;
    const int lid = tid & 31;
    const int p_w   = wid & 3;
    const int khalf = wid >> 2;
    const int r0 = blockIdx.x * 128;

    const float* Asrc = (MODE == 0) ? Ain : g_agg;
    const __half* Bsrc = (MODE == 0) ? g_phB : g_zB;
    float* outp = (MODE == 0) ? g_feat : outparam;

    split_A(Asrc + (size_t)r0 * CC, sA_hi, sA_lo, tid);
    {
        const uint4* tb = (const uint4*)Bsrc;
        uint4* bd = (uint4*)(smem + SM_B_HI);
        #pragma unroll
        for (int i = tid; i < 1152; i += 256) bd[i] = __ldg(&tb[i]);
        if (tid < 64) s_bias[tid] = bias[tid];
        if (MODE == 1 && tid < 128) s_sumw[tid] = g_sumw[r0 + tid];
    }
    __syncthreads();

    float acc[2][8][4];
    gemm_ksplit(sbase, p_w, khalf, lid, acc);

    // epilogue + store (khalf=0 warps)
    if (khalf == 0) {
        const int g = lid >> 2, t = lid & 3;
        #pragma unroll
        for (int mt = 0; mt < 2; ++mt) {
            #pragma unroll
            for (int nt = 0; nt < 8; ++nt) {
                int h = nt * 8 + t * 2;
                float b0 = s_bias[h], b1 = s_bias[h + 1];
                int lr0 = p_w * 32 + g + 16 * mt;
                float v00, v01, v10, v11;
                if (MODE == 0) {
                    v00 = fmaxf(acc[mt][nt][0] + b0, 0.f);
                    v01 = fmaxf(acc[mt][nt][1] + b1, 0.f);
                    v10 = fmaxf(acc[mt][nt][2] + b0, 0.f);
                    v11 = fmaxf(acc[mt][nt][3] + b1, 0.f);
                } else {
                    float s0 = s_sumw[lr0], s1 = s_sumw[lr0 + 8];
                    v00 = fmaf(s0, b0, acc[mt][nt][0]);
                    v01 = fmaf(s0, b1, acc[mt][nt][1]);
                    v10 = fmaf(s1, b0, acc[mt][nt][2]);
                    v11 = fmaf(s1, b1, acc[mt][nt][3]);
                }
                *(float2*)&outp[(size_t)(r0 + lr0) * HH + h]     = make_float2(v00, v01);
                *(float2*)&outp[(size_t)(r0 + lr0 + 8) * HH + h] = make_float2(v10, v11);
            }
        }
    }
}

// ---------- main: K-split HMMA theta GEMM + softmax + aggregation ----------
__global__ void __launch_bounds__(256, 2)
spil_main(const float* __restrict__ neighbor_features,
          const float* __restrict__ theta_b)
{
    extern __shared__ char smem[];
    const uint32_t sbase = smem_to_u32(smem);
    char* sA_hi = smem + SM_A_HI;
    char* sA_lo = smem + SM_A_LO;
    float* s_f    = (float*)(smem + SM_FLT);
    float* s_feat = s_f + F_FEAT;
    float* s_rf   = s_f + F_RF;
    float* s_thb  = s_f + F_THB;

    const int tid = threadIdx.x;
    const int wid = tid >> 5;
    const int lid = tid & 31;
    const int p_w   = wid & 3;
    const int khalf = wid >> 2;
    const int bn0 = blockIdx.x * PTS;

    const float r_l = __ldg(&g_rl[blockIdx.x * 128 + p_w * 32 + lid]);

    split_A(neighbor_features + (size_t)bn0 * KK * CC, sA_hi, sA_lo, tid);
    {
        const uint4* tb = (const uint4*)g_thB;
        uint4* bd = (uint4*)(smem + SM_B_HI);
        #pragma unroll
        for (int i = tid; i < 1152; i += 256) bd[i] = __ldg(&tb[i]);
        if (tid < 64)
            ((uint4*)s_feat)[tid] = __ldg(&((const uint4*)(g_feat + (size_t)bn0 * HH))[tid]);
        if (tid < 64) s_thb[tid] = theta_b[tid];
    }
    __syncthreads();

    float acc[2][8][4];
    gemm_ksplit(sbase, p_w, khalf, lid, acc);

    // r_f reduction (khalf=0 warps, fragment layout)
    if (khalf == 0) {
        const int g = lid >> 2, t = lid & 3;
        const float* fp = s_feat + p_w * HH;
        float r4[4];
        #pragma unroll
        for (int mt = 0; mt < 2; ++mt) {
            float rA = 0.f, rB = 0.f;
            #pragma unroll
            for (int nt = 0; nt < 8; ++nt) {
                int h0 = nt * 8 + t * 2, h1 = h0 + 1;
                float tb0 = s_thb[h0], tb1 = s_thb[h1];
                float f0 = fp[h0], f1 = fp[h1];
                rA = fmaf(fmaxf(acc[mt][nt][0] + tb0, 0.f), f0, rA);
                rA = fmaf(fmaxf(acc[mt][nt][1] + tb1, 0.f), f1, rA);
                rB = fmaf(fmaxf(acc[mt][nt][2] + tb0, 0.f), f0, rB);
                rB = fmaf(fmaxf(acc[mt][nt][3] + tb1, 0.f), f1, rB);
            }
            r4[mt * 2]     = rA;
            r4[mt * 2 + 1] = rB;
        }
        #pragma unroll
        for (int i = 0; i < 4; ++i) {
            r4[i] += __shfl_xor_sync(0xffffffffu, r4[i], 1);
            r4[i] += __shfl_xor_sync(0xffffffffu, r4[i], 2);
        }
        if (t == 0) {
            s_rf[p_w * 32 + g]      = r4[0];
            s_rf[p_w * 32 + g + 8]  = r4[1];
            s_rf[p_w * 32 + g + 16] = r4[2];
            s_rf[p_w * 32 + g + 24] = r4[3];
        }
    }
    __syncthreads();

    // softmax (redundant in both khalf warps of a point)
    float Wk;
    {
        float rf = s_rf[p_w * 32 + lid] * 0.125f;
        float m = rf;
        #pragma unroll
        for (int ofs = 16; ofs > 0; ofs >>= 1) m = fmaxf(m, __shfl_xor_sync(0xffffffffu, m, ofs));
        float e = r_l * __expf(rf - m);
        float s = e;
        #pragma unroll
        for (int ofs = 16; ofs > 0; ofs >>= 1) s += __shfl_xor_sync(0xffffffffu, s, ofs);
        float denom = s + 1e-8f;
        Wk = e / denom;
        if (khalf == 0 && lid == 0) g_sumw[bn0 + p_w] = s / denom;
    }

    // aggregation: warp covers its 64-column half (c = 64*khalf + 2*lid, +1), hi+lo
    {
        float2 a01 = make_float2(0.f, 0.f);
        const uint32_t co = (uint32_t)(128 * khalf + 4 * lid);
        #pragma unroll
        for (int k = 0; k < KK; ++k) {
            float wk = __shfl_sync(0xffffffffu, Wk, k);
            uint32_t o = (uint32_t)((p_w * KK + k) * A_STR) * 2 + co;
            float2 h0 = __half22float2(*(__half2*)(sA_hi + o));
            float2 l0 = __half22float2(*(__half2*)(sA_lo + o));
            a01.x = fmaf(wk, h0.x + l0.x, a01.x);
            a01.y = fmaf(wk, h0.y + l0.y, a01.y);
        }
        float* dst = g_agg + (size_t)(bn0 + p_w) * CC + 64 * khalf;
        *(float2*)&dst[2 * lid] = a01;
    }
}

extern "C" void kernel_launch(void* const* d_in, const int* in_sizes, int n_in,
                              void* d_out, int out_size)
{
    (void)in_sizes; (void)n_in; (void)out_size;
    const float* center_xyz        = (const float*)d_in[0];
    const float* center_features   = (const float*)d_in[1];
    const float* neighbor_xyz      = (const float*)d_in[2];
    const float* neighbor_features = (const float*)d_in[3];
    const float* phi_w   = (const float*)d_in[4];
    const float* phi_b   = (const float*)d_in[5];
    const float* theta_w = (const float*)d_in[6];
    const float* theta_b = (const float*)d_in[7];
    const float* m1_w    = (const float*)d_in[8];
    const float* m1_b    = (const float*)d_in[9];
    const float* m2_w    = (const float*)d_in[10];
    const float* m2_b    = (const float*)d_in[11];
    const float* psi_w   = (const float*)d_in[12];
    const float* psi_b   = (const float*)d_in[13];
    const float* z_w     = (const float*)d_in[14];
    const float* z_b     = (const float*)d_in[15];
    float* out = (float*)d_out;

    cudaFuncSetAttribute(spil_main, cudaFuncAttributeMaxDynamicSharedMemorySize, SMEM_TOTAL);
    cudaFuncSetAttribute(aux_gemm<0>, cudaFuncAttributeMaxDynamicSharedMemorySize, SMEM_TOTAL);
    cudaFuncSetAttribute(aux_gemm<1>, cudaFuncAttributeMaxDynamicSharedMemorySize, SMEM_TOTAL);

    k_pre<<<SI_BLKS + 96, 256>>>(center_xyz, m1_w, m1_b, psi_w, theta_w, phi_w, z_w);
    aux_gemm<0><<<NPTS / 128, 256, SMEM_TOTAL>>>(center_features, phi_b, out);
    k1_rl<<<NPTS * KK / 256, 256>>>(center_xyz, neighbor_xyz, m2_w, m2_b, psi_w, psi_b);
    spil_main<<<NPTS / PTS, 256, SMEM_TOTAL>>>(neighbor_features, theta_b);
    aux_gemm<1><<<NPTS / 128, 256, SMEM_TOTAL>>>(center_features, z_b, out);
}

// round 12
// speedup vs baseline: 1.8204x; 1.3236x over previous
#include <cuda_runtime.h>
#include <cuda_fp16.h>
#include <cstdint>

// SPIL layer pipeline, R12 = R11 with single-pass fp16 in the MAIN kernel.
//   k_pre : stage theta/phi/z -> fp16  |  s_i per point
//   aux<0>: g_feat = relu(cf @ phi_w + b)        [fp16 2-pass, unchanged R11]
//   k1_rl : r_l per (n,k) masked+relu'd
//   main  : SINGLE-PASS fp16 HMMA theta GEMM + softmax + agg (fp16 nf)
//   aux<1>: out = g_agg @ z_w + g_sumw * z_b     [fp16 2-pass, unchanged R11]
// Error budget: measured 2.25e-4 (R11) + theta-A rounding (softmax-damped) +
// agg fp16 (~1.4e-4) -> predicted ~3.5-4e-4 vs 1e-3 threshold.
// Main cuts: MMAs -50%, A-ldsm -50%, split conversion -50%, agg LDS -50%,
// smem 90->55 KB.

#define BB 8
#define NN 4096
#define KK 32
#define CC 128
#define HH 64
#define PP 32
#define PTS 4
#define ROWS 128
#define D_THR 0.04f
#define NPTS (BB*NN)        // 32768

__device__ float g_feat[NPTS * HH];
__device__ float g_si[NPTS];
__device__ float g_rl[NPTS * KK];
__device__ float g_agg[NPTS * CC];
__device__ float g_sumw[NPTS];
#define B_STR 72
__device__ __align__(16) __half g_thB[CC * B_STR];
__device__ __align__(16) __half g_phB[CC * B_STR];
__device__ __align__(16) __half g_zB [CC * B_STR];

#define A_STR 136
// ---- aux smem layout (R11: A hi/lo 2-pass) ----
#define AX_A_HI 0
#define AX_A_LO (AX_A_HI + ROWS * A_STR * 2)   // 34816
#define AX_B    (AX_A_LO + ROWS * A_STR * 2)   // 69632
#define AX_FLT  (AX_B + CC * B_STR * 2)        // 88064
#define AX_TOTAL (AX_FLT + 448 * 4)            // 89856
#define F_BIAS 0
#define F_SUMW 64
// ---- main smem layout (single fp16 A) ----
#define MN_A   0
#define MN_B   (MN_A + ROWS * A_STR * 2)       // 34816
#define MN_FLT (MN_B + CC * B_STR * 2)         // 53248
#define F_FEAT 0      // 256 floats
#define F_RF   256    // 128
#define F_THB  384    // 64
#define MN_TOTAL (MN_FLT + 448 * 4)            // 55040

__device__ __forceinline__ uint32_t smem_to_u32(const void* p) {
    uint32_t a;
    asm("{ .reg .u64 t; cvta.to.shared.u64 t, %1; cvt.u32.u64 %0, t; }" : "=r"(a) : "l"(p));
    return a;
}
__device__ __forceinline__ void ldsm_x4(uint32_t* r, uint32_t addr) {
    asm volatile("ldmatrix.sync.aligned.m8n8.x4.shared.b16 {%0,%1,%2,%3}, [%4];"
                 : "=r"(r[0]), "=r"(r[1]), "=r"(r[2]), "=r"(r[3]) : "r"(addr));
}
__device__ __forceinline__ void ldsm_x4_t(uint32_t* r, uint32_t addr) {
    asm volatile("ldmatrix.sync.aligned.m8n8.x4.trans.shared.b16 {%0,%1,%2,%3}, [%4];"
                 : "=r"(r[0]), "=r"(r[1]), "=r"(r[2]), "=r"(r[3]) : "r"(addr));
}
__device__ __forceinline__ void mma16816(float* d, const uint32_t* a, const uint32_t* b) {
    asm volatile("mma.sync.aligned.m16n8k16.row.col.f32.f16.f16.f32 "
                 "{%0,%1,%2,%3}, {%4,%5,%6,%7}, {%8,%9}, {%0,%1,%2,%3};"
                 : "+f"(d[0]), "+f"(d[1]), "+f"(d[2]), "+f"(d[3])
                 : "r"(a[0]), "r"(a[1]), "r"(a[2]), "r"(a[3]), "r"(b[0]), "r"(b[1]));
}

// ---- A split hi/lo (aux, 2-pass) ----
__device__ __forceinline__ void split_A_hilo(const float* __restrict__ src,
                                             char* sA_hi, char* sA_lo, int tid) {
    const float4* ag = (const float4*)src;
    #pragma unroll
    for (int it = 0; it < 16; ++it) {
        int v4 = it * 256 + tid;
        float4 v = __ldg(&ag[v4]);
        int flat = v4 * 4;
        int row = flat >> 7, c = flat & 127;
        __half2 h01 = __float22half2_rn(make_float2(v.x, v.y));
        __half2 h23 = __float22half2_rn(make_float2(v.z, v.w));
        float2 f01 = __half22float2(h01);
        float2 f23 = __half22float2(h23);
        __half2 l01 = __float22half2_rn(make_float2(v.x - f01.x, v.y - f01.y));
        __half2 l23 = __float22half2_rn(make_float2(v.z - f23.x, v.w - f23.y));
        uint32_t o = (uint32_t)(row * A_STR + c) * 2;
        *(__half2*)(sA_hi + o)     = h01;
        *(__half2*)(sA_hi + o + 4) = h23;
        *(__half2*)(sA_lo + o)     = l01;
        *(__half2*)(sA_lo + o + 4) = l23;
    }
}

// ---- A convert single fp16 (main) ----
__device__ __forceinline__ void conv_A(const float* __restrict__ src,
                                       char* sA, int tid) {
    const float4* ag = (const float4*)src;
    #pragma unroll
    for (int it = 0; it < 16; ++it) {
        int v4 = it * 256 + tid;
        float4 v = __ldg(&ag[v4]);
        int flat = v4 * 4;
        int row = flat >> 7, c = flat & 127;
        __half2 h01 = __float22half2_rn(make_float2(v.x, v.y));
        __half2 h23 = __float22half2_rn(make_float2(v.z, v.w));
        uint2 u;
        u.x = *(uint32_t*)&h01;
        u.y = *(uint32_t*)&h23;
        *(uint2*)(sA + (uint32_t)(row * A_STR + c) * 2) = u;
    }
}

// ---- K-split GEMM core (TWOPASS: + A-lo pass) + 2-round smem D-reduction ----
template <bool TWOPASS>
__device__ __forceinline__ void gemm_core(uint32_t aHi, uint32_t aLo, uint32_t bBase,
                                          uint32_t stageBase, int p_w, int khalf,
                                          int lid, float acc[2][8][4]) {
    #pragma unroll
    for (int mt = 0; mt < 2; ++mt)
        #pragma unroll
        for (int nt = 0; nt < 8; ++nt)
            #pragma unroll
            for (int e = 0; e < 4; ++e) acc[mt][nt][e] = 0.f;

    const uint32_t a_row  = (uint32_t)(p_w * 32 + (lid & 15));
    const uint32_t a_colq = (uint32_t)((lid >> 4) * 8);
    const uint32_t aoff   = (a_row * A_STR + a_colq) * 2;
    const uint32_t b_rowl = (uint32_t)(lid & 15);
    const uint32_t b_colq = (uint32_t)((lid >> 4) * 8);

    #pragma unroll
    for (int j = 0; j < 4; ++j) {
        const int kc = 4 * khalf + j;
        uint32_t ah[2][4], al[2][4];
        ldsm_x4(ah[0], aHi + aoff + (uint32_t)(kc * 32));
        ldsm_x4(ah[1], aHi + aoff + (uint32_t)(kc * 32) + 16 * A_STR * 2);
        if (TWOPASS) {
            ldsm_x4(al[0], aLo + aoff + (uint32_t)(kc * 32));
            ldsm_x4(al[1], aLo + aoff + (uint32_t)(kc * 32) + 16 * A_STR * 2);
        }

        uint32_t brow = (uint32_t)(kc * 16) + b_rowl;
        uint32_t bh[8][2];
        #pragma unroll
        for (int p = 0; p < 4; ++p) {
            uint32_t bo = (brow * B_STR + 16 * p + b_colq) * 2;
            uint32_t r[4];
            ldsm_x4_t(r, bBase + bo);
            bh[2*p][0] = r[0]; bh[2*p][1] = r[1]; bh[2*p+1][0] = r[2]; bh[2*p+1][1] = r[3];
        }
        #pragma unroll
        for (int mt = 0; mt < 2; ++mt)
            #pragma unroll
            for (int nt = 0; nt < 8; ++nt) {
                mma16816(acc[mt][nt], ah[mt], bh[nt]);
                if (TWOPASS) mma16816(acc[mt][nt], al[mt], bh[nt]);
            }
    }
    __syncthreads();   // all B ldsm done -> B region (18KB) becomes D staging

    // 2-round K reduction: 4 slots x 4KB = 16KB staged in dead B region
    uint32_t stage = stageBase + (uint32_t)(p_w * 4096) + (uint32_t)(lid * 16);
    #pragma unroll
    for (int mt = 0; mt < 2; ++mt) {
        if (khalf == 1) {
            #pragma unroll
            for (int nt = 0; nt < 8; ++nt)
                asm volatile("st.shared.v4.f32 [%0], {%1,%2,%3,%4};"
                             :: "r"(stage + nt * 512),
                                "f"(acc[mt][nt][0]), "f"(acc[mt][nt][1]),
                                "f"(acc[mt][nt][2]), "f"(acc[mt][nt][3]) : "memory");
        }
        __syncthreads();
        if (khalf == 0) {
            #pragma unroll
            for (int nt = 0; nt < 8; ++nt) {
                float p0, p1, p2, p3;
                asm volatile("ld.shared.v4.f32 {%0,%1,%2,%3}, [%4];"
                             : "=f"(p0), "=f"(p1), "=f"(p2), "=f"(p3)
                             : "r"(stage + nt * 512));
                acc[mt][nt][0] += p0; acc[mt][nt][1] += p1;
                acc[mt][nt][2] += p2; acc[mt][nt][3] += p3;
            }
        }
        __syncthreads();
    }
}

// ---------- k_pre: fp16 weight staging (theta/phi/z) + s_i ----------
#define SI_BLKS  (NPTS / 256)    // 128
__global__ void __launch_bounds__(256) k_pre(const float* __restrict__ cxyz,
                                             const float* __restrict__ m1w,
                                             const float* __restrict__ m1b,
                                             const float* __restrict__ psiw,
                                             const float* __restrict__ tw,
                                             const float* __restrict__ phiw,
                                             const float* __restrict__ zw) {
    int blk = blockIdx.x;
    int tid = threadIdx.x;
    if (blk < SI_BLKS) {
        __shared__ float sw[96], sb2[32], sp[32];
        if (tid < 96) sw[tid] = m1w[tid];
        if (tid < 32) { sb2[tid] = m1b[tid]; sp[tid] = psiw[tid]; }
        __syncthreads();
        int id = blk * 256 + tid;
        float x = cxyz[id * 3], y = cxyz[id * 3 + 1], z = cxyz[id * 3 + 2];
        float si = 0.f;
        #pragma unroll
        for (int d = 0; d < PP; ++d) {
            float pi = fmaf(x, sw[d], fmaf(y, sw[32 + d], fmaf(z, sw[64 + d], sb2[d])));
            si = fmaf(fmaxf(pi, 0.f), sp[d], si);
        }
        g_si[id] = si;
        return;
    }
    blk -= SI_BLKS;
    int m = blk >> 5;                 // 0: theta, 1: phi, 2: z
    int id = (blk & 31) * 256 + tid;
    const float* src = (m == 0) ? tw : (m == 1) ? phiw : zw;
    __half* dst = (m == 0) ? g_thB : (m == 1) ? g_phB : g_zB;
    int c = id >> 6, h = id & 63;
    dst[c * B_STR + h] = __float2half_rn(src[id]);
}

// ---------- k1_rl ----------
__global__ void __launch_bounds__(256) k1_rl(const float* __restrict__ cxyz,
                                             const float* __restrict__ nxyz,
                                             const float* __restrict__ m2w,
                                             const float* __restrict__ m2b,
                                             const float* __restrict__ psiw,
                                             const float* __restrict__ psib) {
    __shared__ float sw[96], sb[32], sp[32], spb;
    int tid = threadIdx.x;
    if (tid < 96) sw[tid] = m2w[tid];
    if (tid < 32) { sb[tid] = m2b[tid]; sp[tid] = psiw[32 + tid]; }
    if (tid == 0) spb = psib[0];
    __syncthreads();
    int g = blockIdx.x * 256 + tid;
    int nl = g >> 5;
    float nx = nxyz[g * 3], ny = nxyz[g * 3 + 1], nz = nxyz[g * 3 + 2];
    float cx = cxyz[nl * 3], cy = cxyz[nl * 3 + 1], cz = cxyz[nl * 3 + 2];
    float sj = 0.f;
    #pragma unroll
    for (int d = 0; d < PP; ++d) {
        float pj = fmaf(nx, sw[d], fmaf(ny, sw[32 + d], fmaf(nz, sw[64 + d], sb[d])));
        sj = fmaf(fmaxf(pj, 0.f), sp[d], sj);
    }
    float dx = cx - nx, dy = cy - ny, dz = cz - nz;
    float dist = sqrtf(dx * dx + dy * dy + dz * dz);
    bool masked = (cz == nz) && (dist > D_THR);
    g_rl[g] = fmaxf(g_si[nl] + sj + spb, 0.f) * (masked ? 0.f : 1.f);
}

// ---------- aux HMMA GEMM (R11-verbatim, 2-pass A) ----------
// MODE 0: g_feat = relu(cf @ phi_w + bias)
// MODE 1: outp   = g_agg @ z_w + g_sumw[row] * bias
template <int MODE>
__global__ void __launch_bounds__(256, 2)
aux_gemm(const float* __restrict__ Ain, const float* __restrict__ bias,
         float* __restrict__ outparam)
{
    extern __shared__ char smem[];
    const uint32_t sbase = smem_to_u32(smem);
    char* sA_hi = smem + AX_A_HI;
    char* sA_lo = smem + AX_A_LO;
    float* s_f    = (float*)(smem + AX_FLT);
    float* s_bias = s_f + F_BIAS;
    float* s_sumw = s_f + F_SUMW;

    const int tid = threadIdx.x;
    const int wid = tid >> 5;
    const int lid = tid & 31;
    const int p_w   = wid & 3;
    const int khalf = wid >> 2;
    const int r0 = blockIdx.x * 128;

    const float* Asrc = (MODE == 0) ? Ain : g_agg;
    const __half* Bsrc = (MODE == 0) ? g_phB : g_zB;
    float* outp = (MODE == 0) ? g_feat : outparam;

    split_A_hilo(Asrc + (size_t)r0 * CC, sA_hi, sA_lo, tid);
    {
        const uint4* tb = (const uint4*)Bsrc;
        uint4* bd = (uint4*)(smem + AX_B);
        #pragma unroll
        for (int i = tid; i < 1152; i += 256) bd[i] = __ldg(&tb[i]);
        if (tid < 64) s_bias[tid] = bias[tid];
        if (MODE == 1 && tid < 128) s_sumw[tid] = g_sumw[r0 + tid];
    }
    __syncthreads();

    float acc[2][8][4];
    gemm_core<true>(sbase + AX_A_HI, sbase + AX_A_LO, sbase + AX_B,
                    sbase + AX_B, p_w, khalf, lid, acc);

    if (khalf == 0) {
        const int g = lid >> 2, t = lid & 3;
        #pragma unroll
        for (int mt = 0; mt < 2; ++mt) {
            #pragma unroll
            for (int nt = 0; nt < 8; ++nt) {
                int h = nt * 8 + t * 2;
                float b0 = s_bias[h], b1 = s_bias[h + 1];
                int lr0 = p_w * 32 + g + 16 * mt;
                float v00, v01, v10, v11;
                if (MODE == 0) {
                    v00 = fmaxf(acc[mt][nt][0] + b0, 0.f);
                    v01 = fmaxf(acc[mt][nt][1] + b1, 0.f);
                    v10 = fmaxf(acc[mt][nt][2] + b0, 0.f);
                    v11 = fmaxf(acc[mt][nt][3] + b1, 0.f);
                } else {
                    float s0 = s_sumw[lr0], s1 = s_sumw[lr0 + 8];
                    v00 = fmaf(s0, b0, acc[mt][nt][0]);
                    v01 = fmaf(s0, b1, acc[mt][nt][1]);
                    v10 = fmaf(s1, b0, acc[mt][nt][2]);
                    v11 = fmaf(s1, b1, acc[mt][nt][3]);
                }
                *(float2*)&outp[(size_t)(r0 + lr0) * HH + h]     = make_float2(v00, v01);
                *(float2*)&outp[(size_t)(r0 + lr0 + 8) * HH + h] = make_float2(v10, v11);
            }
        }
    }
}

// ---------- main: single-pass fp16 theta GEMM + softmax + aggregation ----------
__global__ void __launch_bounds__(256, 2)
spil_main(const float* __restrict__ neighbor_features,
          const float* __restrict__ theta_b)
{
    extern __shared__ char smem[];
    const uint32_t sbase = smem_to_u32(smem);
    char* sA = smem + MN_A;
    float* s_f    = (float*)(smem + MN_FLT);
    float* s_feat = s_f + F_FEAT;
    float* s_rf   = s_f + F_RF;
    float* s_thb  = s_f + F_THB;

    const int tid = threadIdx.x;
    const int wid = tid >> 5;
    const int lid = tid & 31;
    const int p_w   = wid & 3;
    const int khalf = wid >> 2;
    const int bn0 = blockIdx.x * PTS;

    const float r_l = __ldg(&g_rl[blockIdx.x * 128 + p_w * 32 + lid]);

    conv_A(neighbor_features + (size_t)bn0 * KK * CC, sA, tid);
    {
        const uint4* tb = (const uint4*)g_thB;
        uint4* bd = (uint4*)(smem + MN_B);
        #pragma unroll
        for (int i = tid; i < 1152; i += 256) bd[i] = __ldg(&tb[i]);
        if (tid < 64)
            ((uint4*)s_feat)[tid] = __ldg(&((const uint4*)(g_feat + (size_t)bn0 * HH))[tid]);
        if (tid < 64) s_thb[tid] = theta_b[tid];
    }
    __syncthreads();

    float acc[2][8][4];
    gemm_core<false>(sbase + MN_A, 0u, sbase + MN_B,
                     sbase + MN_B, p_w, khalf, lid, acc);

    // r_f reduction (khalf=0 warps, fragment layout)
    if (khalf == 0) {
        const int g = lid >> 2, t = lid & 3;
        const float* fp = s_feat + p_w * HH;
        float r4[4];
        #pragma unroll
        for (int mt = 0; mt < 2; ++mt) {
            float rA = 0.f, rB = 0.f;
            #pragma unroll
            for (int nt = 0; nt < 8; ++nt) {
                int h0 = nt * 8 + t * 2, h1 = h0 + 1;
                float tb0 = s_thb[h0], tb1 = s_thb[h1];
                float f0 = fp[h0], f1 = fp[h1];
                rA = fmaf(fmaxf(acc[mt][nt][0] + tb0, 0.f), f0, rA);
                rA = fmaf(fmaxf(acc[mt][nt][1] + tb1, 0.f), f1, rA);
                rB = fmaf(fmaxf(acc[mt][nt][2] + tb0, 0.f), f0, rB);
                rB = fmaf(fmaxf(acc[mt][nt][3] + tb1, 0.f), f1, rB);
            }
            r4[mt * 2]     = rA;
            r4[mt * 2 + 1] = rB;
        }
        #pragma unroll
        for (int i = 0; i < 4; ++i) {
            r4[i] += __shfl_xor_sync(0xffffffffu, r4[i], 1);
            r4[i] += __shfl_xor_sync(0xffffffffu, r4[i], 2);
        }
        if (t == 0) {
            s_rf[p_w * 32 + g]      = r4[0];
            s_rf[p_w * 32 + g + 8]  = r4[1];
            s_rf[p_w * 32 + g + 16] = r4[2];
            s_rf[p_w * 32 + g + 24] = r4[3];
        }
    }
    __syncthreads();

    // softmax (redundant in both khalf warps of a point)
    float Wk;
    {
        float rf = s_rf[p_w * 32 + lid] * 0.125f;
        float m = rf;
        #pragma unroll
        for (int ofs = 16; ofs > 0; ofs >>= 1) m = fmaxf(m, __shfl_xor_sync(0xffffffffu, m, ofs));
        float e = r_l * __expf(rf - m);
        float s = e;
        #pragma unroll
        for (int ofs = 16; ofs > 0; ofs >>= 1) s += __shfl_xor_sync(0xffffffffu, s, ofs);
        float denom = s + 1e-8f;
        Wk = e / denom;
        if (khalf == 0 && lid == 0) g_sumw[bn0 + p_w] = s / denom;
    }

    // aggregation: warp covers its 64-column half (c = 64*khalf + 2*lid, +1), fp16 nf
    {
        float2 a01 = make_float2(0.f, 0.f);
        const uint32_t co = (uint32_t)(128 * khalf + 4 * lid);
        #pragma unroll
        for (int k = 0; k < KK; ++k) {
            float wk = __shfl_sync(0xffffffffu, Wk, k);
            uint32_t o = (uint32_t)((p_w * KK + k) * A_STR) * 2 + co;
            float2 h0 = __half22float2(*(__half2*)(sA + o));
            a01.x = fmaf(wk, h0.x, a01.x);
            a01.y = fmaf(wk, h0.y, a01.y);
        }
        float* dst = g_agg + (size_t)(bn0 + p_w) * CC + 64 * khalf;
        *(float2*)&dst[2 * lid] = a01;
    }
}

extern "C" void kernel_launch(void* const* d_in, const int* in_sizes, int n_in,
                              void* d_out, int out_size)
{
    (void)in_sizes; (void)n_in; (void)out_size;
    const float* center_xyz        = (const float*)d_in[0];
    const float* center_features   = (const float*)d_in[1];
    const float* neighbor_xyz      = (const float*)d_in[2];
    const float* neighbor_features = (const float*)d_in[3];
    const float* phi_w   = (const float*)d_in[4];
    const float* phi_b   = (const float*)d_in[5];
    const float* theta_w = (const float*)d_in[6];
    const float* theta_b = (const float*)d_in[7];
    const float* m1_w    = (const float*)d_in[8];
    const float* m1_b    = (const float*)d_in[9];
    const float* m2_w    = (const float*)d_in[10];
    const float* m2_b    = (const float*)d_in[11];
    const float* psi_w   = (const float*)d_in[12];
    const float* psi_b   = (const float*)d_in[13];
    const float* z_w     = (const float*)d_in[14];
    const float* z_b     = (const float*)d_in[15];
    float* out = (float*)d_out;

    cudaFuncSetAttribute(spil_main, cudaFuncAttributeMaxDynamicSharedMemorySize, MN_TOTAL);
    cudaFuncSetAttribute(aux_gemm<0>, cudaFuncAttributeMaxDynamicSharedMemorySize, AX_TOTAL);
    cudaFuncSetAttribute(aux_gemm<1>, cudaFuncAttributeMaxDynamicSharedMemorySize, AX_TOTAL);

    k_pre<<<SI_BLKS + 96, 256>>>(center_xyz, m1_w, m1_b, psi_w, theta_w, phi_w, z_w);
    aux_gemm<0><<<NPTS / 128, 256, AX_TOTAL>>>(center_features, phi_b, out);
    k1_rl<<<NPTS * KK / 256, 256>>>(center_xyz, neighbor_xyz, m2_w, m2_b, psi_w, psi_b);
    spil_main<<<NPTS / PTS, 256, MN_TOTAL>>>(neighbor_features, theta_b);
    aux_gemm<1><<<NPTS / 128, 256, AX_TOTAL>>>(center_features, z_b, out);
}